// round 12
// baseline (speedup 1.0000x reference)
#include <cuda_runtime.h>
#include <math.h>

#define NXD 32
#define HID 256
#define NOUT 528
#define BM 32
#define NTHREADS 256
#define HSTR 36
#define LSTRIDE 530

// shared layout (float offsets), total 28352 floats = 113408 B -> 2 blocks/SM
#define OFF_H2 0        // 256*36 = 9216
#define OFF_W0 9216     // 4*272 = 1088
#define OFF_W1 10304    // 4*272 = 1088
#define OFF_L  11392    // 32*530 = 16960 (overlays X and H1)
#define OFF_X  11392    // 32*36 = 1152   (dead after G1)
#define OFF_H1 12544    // 256*36 = 9216  (dead after G2)
#define SMEM_FLOATS 28352

typedef unsigned long long u64;

__device__ __forceinline__ u64 pk2(float lo, float hi) {
    u64 d; asm("mov.b64 %0, {%1, %2};" : "=l"(d) : "f"(lo), "f"(hi)); return d;
}
__device__ __forceinline__ void fma2(u64& d, u64 a, u64 b) {
    asm("fma.rn.f32x2 %0, %1, %2, %0;" : "+l"(d) : "l"(a), "l"(b));
}
__device__ __forceinline__ float2 up2(u64 d) {
    float2 r; asm("mov.b64 {%0, %1}, %2;" : "=f"(r.x), "=f"(r.y) : "l"(d)); return r;
}
__device__ __forceinline__ float ftanh(float x) {
    x = fminf(fmaxf(x, -15.f), 15.f);
    float e = __expf(2.f * x);
    return __fdividef(e - 1.f, e + 1.f);
}
__device__ __forceinline__ float fsplus(float v) {
    float sp = (v > 20.f) ? v : __logf(1.f + __expf(v));
    return fminf(fmaxf(sp + 0.01f, 0.01f), 100.f);
}

// Block 32s x 256c, 8 warps. Warp wp owns cols [32wp, 32wp+32).
// Lane (r=tx>>2, c=tx&3): samples 4r..4r+3; col-pairs (32wp+2c+8t, +1), t=0..3.
// acc[si][t] = f32x2 over the col pair for sample 4r+si.
//   w operand = raw LDS.64 (pre-paired, zero movs); h = LDS.128 + 4 dup movs.
// MODE 0: tanh -> transposed outp[col*HSTR + s]   (h1/h2)
// MODE 1: G3 cols [0,256): wp==0 -> softplus (cols<32) else 0.1*tanh -> sL
// MODE 2: G3 cols [256,512) + tail pair (512+2wp, 513+2wp) via accT -> sL
template<int KTOT, int NCOLS, int MODE>
__device__ __forceinline__ void gemm_tile(
    float* sm, const float* __restrict__ Wg, int ldw,
    const float* __restrict__ bias,
    const float* sHin, float* outp,
    int sbase, int wp, int tx)
{
    const int NCH = KTOT / 4;
    const int NF4 = NCOLS / 4 * 4;          // float4s per 4-row chunk == NCOLS
    const int cb = 32 * wp + 2 * (tx & 3);  // first col of pair t=0
    const int tid = threadIdx.x;

    u64 acc[4][4];
    #pragma unroll
    for (int t = 0; t < 4; t++) {
        float2 bv = *(const float2*)&bias[cb + 8 * t];
        u64 bd = pk2(bv.x, bv.y);
        #pragma unroll
        for (int si = 0; si < 4; si++) acc[si][t] = bd;
    }
    u64 accT[4];
    if (MODE == 2) {
        float2 bv = *(const float2*)&bias[256 + 2 * wp];
        u64 bd = pk2(bv.x, bv.y);
        #pragma unroll
        for (int si = 0; si < 4; si++) accT[si] = bd;
    }

    float* buf0 = sm + OFF_W0;
    float* buf1 = sm + OFF_W1;
    float4 rg0, rg1;

    auto stage_ld = [&](int ch) {
        int row = tid / (NCOLS / 4), c4 = tid % (NCOLS / 4);
        rg0 = *(const float4*)&Wg[(size_t)(ch * 4 + row) * ldw + 4 * c4];
        if (NCOLS > 256 && tid < NF4 - 256) {
            int idx = tid + 256;
            int row2 = idx / (NCOLS / 4), c42 = idx % (NCOLS / 4);
            rg1 = *(const float4*)&Wg[(size_t)(ch * 4 + row2) * ldw + 4 * c42];
        }
    };
    auto stage_st = [&](float* buf) {
        int row = tid / (NCOLS / 4), c4 = tid % (NCOLS / 4);
        *(float4*)&buf[row * NCOLS + 4 * c4] = rg0;
        if (NCOLS > 256 && tid < NF4 - 256) {
            int idx = tid + 256;
            int row2 = idx / (NCOLS / 4), c42 = idx % (NCOLS / 4);
            *(float4*)&buf[row2 * NCOLS + 4 * c42] = rg1;
        }
    };

    stage_ld(0);
    stage_st(buf0);
    __syncthreads();

    for (int ch = 0; ch < NCH; ch++) {
        float* cur = (ch & 1) ? buf1 : buf0;
        float* nxt = (ch & 1) ? buf0 : buf1;
        if (ch + 1 < NCH) stage_ld(ch + 1);
        #pragma unroll
        for (int kk = 0; kk < 4; kk++) {
            float4 h4 = *(const float4*)&sHin[(4 * ch + kk) * HSTR + sbase];
            u64 hd0 = pk2(h4.x, h4.x), hd1 = pk2(h4.y, h4.y);
            u64 hd2 = pk2(h4.z, h4.z), hd3 = pk2(h4.w, h4.w);
            const float* wrow = cur + kk * NCOLS + cb;
            #pragma unroll
            for (int t = 0; t < 4; t++) {
                u64 wv = *(const u64*)(wrow + 8 * t);
                fma2(acc[0][t], hd0, wv);
                fma2(acc[1][t], hd1, wv);
                fma2(acc[2][t], hd2, wv);
                fma2(acc[3][t], hd3, wv);
            }
            if (MODE == 2) {
                u64 wt = *(const u64*)(cur + kk * NCOLS + 256 + 2 * wp);
                fma2(accT[0], hd0, wt);
                fma2(accT[1], hd1, wt);
                fma2(accT[2], hd2, wt);
                fma2(accT[3], hd3, wt);
            }
        }
        if (ch + 1 < NCH) stage_st(nxt);
        __syncthreads();
    }

    // epilogue
    if (MODE == 0) {
        #pragma unroll
        for (int si = 0; si < 4; si++) {
            const int s = sbase + si;
            #pragma unroll
            for (int t = 0; t < 4; t++) {
                float2 v = up2(acc[si][t]);
                const int c0 = cb + 8 * t;
                outp[c0 * HSTR + s]       = ftanh(v.x);
                outp[(c0 + 1) * HSTR + s] = ftanh(v.y);
            }
        }
    } else {
        const bool dg = (MODE == 1) && (wp == 0);   // warp-uniform diag path
        #pragma unroll
        for (int si = 0; si < 4; si++) {
            const int s = sbase + si;
            float* Ls = outp + s * LSTRIDE + ((MODE == 2) ? 256 : 0);
            #pragma unroll
            for (int t = 0; t < 4; t++) {
                float2 v = up2(acc[si][t]);
                float2 o;
                if (dg) { o.x = fsplus(v.x); o.y = fsplus(v.y); }
                else    { o.x = 0.1f * ftanh(v.x); o.y = 0.1f * ftanh(v.y); }
                *(float2*)&Ls[cb + 8 * t] = o;
            }
        }
        if (MODE == 2 && (tx & 3) == 0) {
            #pragma unroll
            for (int si = 0; si < 4; si++) {
                const int s = sbase + si;
                float2 v = up2(accT[si]);
                outp[s * LSTRIDE + 512 + 2 * wp] = 0.1f * ftanh(v.x);
                outp[s * LSTRIDE + 513 + 2 * wp] = 0.1f * ftanh(v.y);
            }
        }
    }
}

__global__ void __launch_bounds__(NTHREADS, 2) covnet_kernel(
    const float* __restrict__ P_prev,
    const float* __restrict__ W1, const float* __restrict__ b1,
    const float* __restrict__ W2, const float* __restrict__ b2,
    const float* __restrict__ W3, const float* __restrict__ b3,
    const float* __restrict__ Q, float* __restrict__ out)
{
    extern __shared__ float sm[];
    const int tid = threadIdx.x;
    const int tx = tid & 31;
    const int wp = tid >> 5;            // 0..7 (col group)
    const int sbase = 4 * (tx >> 2);    // 8 sample groups of 4
    const size_t b0 = (size_t)blockIdx.x * BM;

    // gather diagonal (transposed): sX[d*HSTR + s] = log(clip(P_prev[s,d,d]))
    for (int i = tid; i < NXD * BM; i += NTHREADS) {
        int d = i >> 5, s = i & 31;
        float v = P_prev[(b0 + (size_t)s) * 1024 + d * 33];
        sm[OFF_X + d * HSTR + s] = __logf(fmaxf(v, 1e-6f));
    }
    __syncthreads();

    gemm_tile<32,  256, 0>(sm, W1,       HID,  b1,       sm + OFF_X,  sm + OFF_H1, sbase, wp, tx);
    __syncthreads();
    gemm_tile<256, 256, 0>(sm, W2,       HID,  b2,       sm + OFF_H1, sm + OFF_H2, sbase, wp, tx);
    __syncthreads();
    gemm_tile<256, 256, 1>(sm, W3,       NOUT, b3,       sm + OFF_H2, sm + OFF_L,  sbase, wp, tx);
    __syncthreads();
    gemm_tile<256, 272, 2>(sm, W3 + 256, NOUT, b3 + 256, sm + OFF_H2, sm + OFF_L,  sbase, wp, tx);
    __syncthreads();

    // ================= P = L * L^T + Q =================
    // warp wp handles samples 4wp..4wp+3; lane k owns output column k.
    // Q column k cached in registers; row k gathered; other rows via shfl.
    {
        const int k = tx;
        float Qk[32];
        #pragma unroll
        for (int i = 0; i < 32; i++) Qk[i] = __ldg(&Q[i * 32 + k]);
        const int kb = 32 + k * (k - 1) / 2;

        #pragma unroll 1
        for (int ss = 0; ss < 4; ss++) {
            const int s = 4 * wp + ss;
            const float* Lr = sm + OFF_L + s * LSTRIDE;

            float Lk[32];
            #pragma unroll
            for (int j = 0; j < 32; j++) {
                float tv = 0.f;
                int addr = (j < k) ? (kb + j) : j;   // lower part or diagonal
                if (j <= k) tv = Lr[addr];
                Lk[j] = tv;
            }

            float* Po = out + (b0 + (size_t)s) * 1024;
            #pragma unroll
            for (int i = 0; i < 32; i++) {
                float a = Qk[i];
                #pragma unroll
                for (int j = 0; j <= i; j++)
                    a += __shfl_sync(0xffffffffu, Lk[j], i) * Lk[j];
                Po[i * 32 + k] = a;
            }
        }
    }
}

extern "C" void kernel_launch(void* const* d_in, const int* in_sizes, int n_in,
                              void* d_out, int out_size) {
    const float* P_prev = (const float*)d_in[0];
    const float* W1 = (const float*)d_in[1];
    const float* b1 = (const float*)d_in[2];
    const float* W2 = (const float*)d_in[3];
    const float* b2 = (const float*)d_in[4];
    const float* W3 = (const float*)d_in[5];
    const float* b3 = (const float*)d_in[6];
    const float* Q  = (const float*)d_in[7];
    float* out = (float*)d_out;

    const int B = in_sizes[0] / (NXD * NXD);   // 65536
    const int grid = B / BM;                   // 2048

    cudaFuncSetAttribute(covnet_kernel,
                         cudaFuncAttributeMaxDynamicSharedMemorySize,
                         SMEM_FLOATS * sizeof(float));

    covnet_kernel<<<grid, NTHREADS, SMEM_FLOATS * sizeof(float)>>>(
        P_prev, W1, b1, W2, b2, W3, b3, Q, out);
}

// round 14
// speedup vs baseline: 1.2675x; 1.2675x over previous
#include <cuda_runtime.h>
#include <math.h>

#define NXD 32
#define HID 256
#define NOUT 528
#define BM 32
#define NTHREADS 128
#define LSTRIDE 529
#define HSTR 36

// shared layout (float offsets), total 28320 floats = 113280 B -> 2 blocks/SM
#define OFF_H2 0        // 256*36 = 9216
#define OFF_W  9216     // 8*256 = 2048 (single buffer, rounded region 2176)
#define OFF_L  11392    // 32*529 = 16928 (overlays X and H1)
#define OFF_X  11392    // 32*36 = 1152   (dead after G1)
#define OFF_H1 12544    // 256*36 = 9216  (dead after G2)
#define SMEM_FLOATS 28320

typedef unsigned long long u64;

__device__ __forceinline__ u64 pk2(float lo, float hi) {
    u64 d; asm("mov.b64 %0, {%1, %2};" : "=l"(d) : "f"(lo), "f"(hi)); return d;
}
__device__ __forceinline__ void fma2(u64& d, u64 a, u64 b) {
    asm("fma.rn.f32x2 %0, %1, %2, %0;" : "+l"(d) : "l"(a), "l"(b));
}
__device__ __forceinline__ float2 up2(u64 d) {
    float2 r; asm("mov.b64 {%0, %1}, %2;" : "=f"(r.x), "=f"(r.y) : "l"(d)); return r;
}
__device__ __forceinline__ float ftanh(float x) {
    x = fminf(fmaxf(x, -15.f), 15.f);
    float e = __expf(2.f * x);
    return __fdividef(e - 1.f, e + 1.f);
}
__device__ __forceinline__ float fsplus(float v) {
    float sp = (v > 20.f) ? v : __logf(1.f + __expf(v));
    return fminf(fmaxf(sp + 0.01f, 0.01f), 100.f);
}

// Block 32s x 256c, 4 warps. Warp wp owns cols {64wp + c + 8t : t=0..7} (span 64, no overlap).
// Lane (r=tx>>3, c=tx&7): samples sbase=8r..8r+7 ; cols cb=64wp+c, stride 8.
// acc[sp][t] = f32x2 over samples (sbase+2sp, sbase+2sp+1), col cb+8t.
//   h = 2 raw LDS.128 (sample-pair u64s, zero movs); w = 8 scalar LDS + dup movs.
// MODE 0: tanh -> transposed outp[col*HSTR + s]   (h1/h2)
// MODE 1: G3 cols [0,256): wp==0 && t<4 -> softplus (cols<32) else 0.1*tanh -> sL
// MODE 2: G3 cols [256,512): 0.1*tanh -> sL (tail cols 512.. handled separately)
template<int KTOT, int MODE>
__device__ __forceinline__ void gemm_tile(
    float* sm, const float* __restrict__ Wg, int ldw,
    const float* __restrict__ bias,
    const float* sHin, float* outp,
    int sbase, int wp, int tx)
{
    const int NCH = KTOT / 8;
    const int c  = tx & 7;
    const int cb = 64 * wp + c;
    const int tid = threadIdx.x;
    float* sW = sm + OFF_W;

    u64 acc[4][8];
    #pragma unroll
    for (int t = 0; t < 8; t++) {
        float bv = __ldg(&bias[cb + 8 * t]);
        u64 bd = pk2(bv, bv);
        #pragma unroll
        for (int sp = 0; sp < 4; sp++) acc[sp][t] = bd;
    }

    // staging regs: 8x256 chunk = 512 float4, 128 threads -> 4 each
    float4 rg[4];
    auto stage_ld = [&](int ch) {
        #pragma unroll
        for (int rep = 0; rep < 4; rep++) {
            int idx = tid + 128 * rep;
            int row = idx >> 6, c4 = idx & 63;
            rg[rep] = *(const float4*)&Wg[(size_t)(ch * 8 + row) * ldw + 4 * c4];
        }
    };
    auto stage_st = [&]() {
        #pragma unroll
        for (int rep = 0; rep < 4; rep++) {
            int idx = tid + 128 * rep;
            int row = idx >> 6, c4 = idx & 63;
            *(float4*)&sW[row * 256 + 4 * c4] = rg[rep];
        }
    };

    stage_ld(0);
    stage_st();           // safe: previous phase's mainloop ended with a barrier
    __syncthreads();      // also orders previous epilogue's sHin writes

    for (int ch = 0; ch < NCH; ch++) {
        if (ch + 1 < NCH) stage_ld(ch + 1);
        #pragma unroll
        for (int kk = 0; kk < 8; kk++) {
            const float* hrow = sHin + (8 * ch + kk) * HSTR + sbase;
            ulonglong2 hA = *(const ulonglong2*)hrow;        // samples sbase..+3
            ulonglong2 hB = *(const ulonglong2*)(hrow + 4);  // samples +4..+7
            u64 hd0 = hA.x, hd1 = hA.y, hd2 = hB.x, hd3 = hB.y;
            const float* wrow = sW + kk * 256;
            #pragma unroll
            for (int t = 0; t < 8; t++) {
                float wv = wrow[cb + 8 * t];
                u64 wd = pk2(wv, wv);
                fma2(acc[0][t], hd0, wd);
                fma2(acc[1][t], hd1, wd);
                fma2(acc[2][t], hd2, wd);
                fma2(acc[3][t], hd3, wd);
            }
        }
        __syncthreads();                       // everyone done reading sW
        if (ch + 1 < NCH) { stage_st(); __syncthreads(); }
    }

    // epilogue
    if (MODE == 0) {
        #pragma unroll
        for (int t = 0; t < 8; t++) {
            const int col = cb + 8 * t;
            #pragma unroll
            for (int sp = 0; sp < 4; sp++) {
                float2 v = up2(acc[sp][t]);
                float2 o = { ftanh(v.x), ftanh(v.y) };
                *(float2*)&outp[col * HSTR + sbase + 2 * sp] = o;
            }
        }
    } else {
        #pragma unroll
        for (int sp = 0; sp < 4; sp++) {
            #pragma unroll
            for (int e = 0; e < 2; e++) {
                const int s = sbase + 2 * sp + e;
                float* Ls = outp + s * LSTRIDE + ((MODE == 2) ? 256 : 0);
                #pragma unroll
                for (int t = 0; t < 8; t++) {
                    float2 v = up2(acc[sp][t]);
                    float val = e ? v.y : v.x;
                    bool dg = (MODE == 1) && (wp == 0) && (t < 4); // global col < 32
                    Ls[cb + 8 * t] = dg ? fsplus(val) : 0.1f * ftanh(val);
                }
            }
        }
    }
}

__global__ void __launch_bounds__(NTHREADS, 2) covnet_kernel(
    const float* __restrict__ P_prev,
    const float* __restrict__ W1, const float* __restrict__ b1,
    const float* __restrict__ W2, const float* __restrict__ b2,
    const float* __restrict__ W3, const float* __restrict__ b3,
    const float* __restrict__ Q, float* __restrict__ out)
{
    extern __shared__ float sm[];
    const int tid = threadIdx.x;
    const int tx = tid & 31;
    const int wp = tid >> 5;            // 0..3
    const int sbase = 8 * (tx >> 3);    // 4 sample groups of 8
    const size_t b0 = (size_t)blockIdx.x * BM;

    // gather diagonal (transposed): sX[d*HSTR + s] = log(clip(P_prev[s,d,d]))
    for (int i = tid; i < NXD * BM; i += NTHREADS) {
        int d = i >> 5, s = i & 31;
        float v = P_prev[(b0 + (size_t)s) * 1024 + d * 33];
        sm[OFF_X + d * HSTR + s] = __logf(fmaxf(v, 1e-6f));
    }
    __syncthreads();

    gemm_tile<32,  0>(sm, W1,       HID,  b1,       sm + OFF_X,  sm + OFF_H1, sbase, wp, tx);
    gemm_tile<256, 0>(sm, W2,       HID,  b2,       sm + OFF_H1, sm + OFF_H2, sbase, wp, tx);
    gemm_tile<256, 1>(sm, W3,       NOUT, b3,       sm + OFF_H2, sm + OFF_L,  sbase, wp, tx);
    gemm_tile<256, 2>(sm, W3 + 256, NOUT, b3 + 256, sm + OFF_H2, sm + OFF_L,  sbase, wp, tx);

    // ====== GEMM3 tail: cols [512, 528) — lane s=tx, warp wp -> cols 512+4wp..+3
    {
        const int s = tx;
        float a[4];
        float4 bt = *(const float4*)&b3[512 + 4 * wp];
        a[0] = bt.x; a[1] = bt.y; a[2] = bt.z; a[3] = bt.w;
        const float* hr = sm + OFF_H2;
        #pragma unroll 8
        for (int k = 0; k < HID; k++) {
            float hv = hr[k * HSTR + s];
            float4 w = __ldg((const float4*)&W3[(size_t)k * NOUT + 512 + 4 * wp]);
            a[0] += hv * w.x; a[1] += hv * w.y;
            a[2] += hv * w.z; a[3] += hv * w.w;
        }
        float* Ls = sm + OFF_L + s * LSTRIDE + 512 + 4 * wp;
        #pragma unroll
        for (int q = 0; q < 4; q++) Ls[q] = 0.1f * ftanh(a[q]);
    }
    __syncthreads();

    // ================= P = L * L^T + Q =================
    // warp wp handles samples 8wp..8wp+7; lane k owns output column k.
    {
        const int k = tx;
        float Qk[32];
        #pragma unroll
        for (int i = 0; i < 32; i++) Qk[i] = __ldg(&Q[i * 32 + k]);
        const int kb = 32 + k * (k - 1) / 2;

        #pragma unroll 1
        for (int ss = 0; ss < 8; ss++) {
            const int s = 8 * wp + ss;
            const float* Lr = sm + OFF_L + s * LSTRIDE;

            float Lk[32];
            #pragma unroll
            for (int j = 0; j < 32; j++) {
                float tv = 0.f;
                int addr = (j < k) ? (kb + j) : j;   // lower part or diagonal
                if (j <= k) tv = Lr[addr];
                Lk[j] = tv;
            }

            float* Po = out + (b0 + (size_t)s) * 1024;
            #pragma unroll
            for (int i = 0; i < 32; i++) {
                float a = Qk[i];
                #pragma unroll
                for (int j = 0; j <= i; j++)
                    a += __shfl_sync(0xffffffffu, Lk[j], i) * Lk[j];
                Po[i * 32 + k] = a;
            }
        }
    }
}

extern "C" void kernel_launch(void* const* d_in, const int* in_sizes, int n_in,
                              void* d_out, int out_size) {
    const float* P_prev = (const float*)d_in[0];
    const float* W1 = (const float*)d_in[1];
    const float* b1 = (const float*)d_in[2];
    const float* W2 = (const float*)d_in[3];
    const float* b2 = (const float*)d_in[4];
    const float* W3 = (const float*)d_in[5];
    const float* b3 = (const float*)d_in[6];
    const float* Q  = (const float*)d_in[7];
    float* out = (float*)d_out;

    const int B = in_sizes[0] / (NXD * NXD);   // 65536
    const int grid = B / BM;                   // 2048

    cudaFuncSetAttribute(covnet_kernel,
                         cudaFuncAttributeMaxDynamicSharedMemorySize,
                         SMEM_FLOATS * sizeof(float));

    covnet_kernel<<<grid, NTHREADS, SMEM_FLOATS * sizeof(float)>>>(
        P_prev, W1, b1, W2, b2, W3, b3, Q, out);
}